// round 15
// baseline (speedup 1.0000x reference)
#include <cuda_runtime.h>
#include <cuda_fp16.h>
#include <stdint.h>
#include <math.h>

// Problem constants: B=4, C=64, H=W=64, P=4096.
#define BATCH 4
#define CCH   64
#define PPIX  4096
#define LOG2E 1.4426950408889634f
#define PSH   14.0f                 // pack scale: p' = 2^(s*log2e - M + 14) <= 2^14
#define KLSCALE 256.0f
#define KLINV  0.00390625f

// ---------------------------------------------------------------------------
// Device scratch. fp16 split x = hi + lo (~22 bits). Kl stored *256.
// ---------------------------------------------------------------------------
__device__ __half g_Qh[BATCH * PPIX * CCH];  // Y boxsum  [b][p][c]
__device__ __half g_Ql[BATCH * PPIX * CCH];
__device__ __half g_Kh[BATCH * PPIX * CCH];  // K-hat     [b][p][c]  (also V)
__device__ __half g_Kl[BATCH * PPIX * CCH];  // (K - Kh) * 256

// ---------------------------------------------------------------------------
// helpers (baseline PTX only: mma.sync / ldmatrix / cp.async)
// ---------------------------------------------------------------------------
__device__ __forceinline__ uint32_t smem_u32(const void* p) {
    uint32_t a;
    asm("{ .reg .u64 t; cvta.to.shared.u64 t, %1; cvt.u32.u64 %0, t; }" : "=r"(a) : "l"(p));
    return a;
}
__device__ __forceinline__ void ldsm4(uint32_t* r, uint32_t addr) {   // non-trans
    asm volatile("ldmatrix.sync.aligned.m8n8.x4.shared.b16 {%0,%1,%2,%3}, [%4];"
        : "=r"(r[0]), "=r"(r[1]), "=r"(r[2]), "=r"(r[3]) : "r"(addr));
}
__device__ __forceinline__ void ldsm4t(uint32_t* r, uint32_t addr) {  // trans
    asm volatile("ldmatrix.sync.aligned.m8n8.x4.trans.shared.b16 {%0,%1,%2,%3}, [%4];"
        : "=r"(r[0]), "=r"(r[1]), "=r"(r[2]), "=r"(r[3]) : "r"(addr));
}
__device__ __forceinline__ void mma16816(float* d, const uint32_t* a, uint32_t b0, uint32_t b1) {
    asm volatile(
        "mma.sync.aligned.m16n8k16.row.col.f32.f16.f16.f32 "
        "{%0,%1,%2,%3}, {%4,%5,%6,%7}, {%8,%9}, {%0,%1,%2,%3};"
        : "+f"(d[0]), "+f"(d[1]), "+f"(d[2]), "+f"(d[3])
        : "r"(a[0]), "r"(a[1]), "r"(a[2]), "r"(a[3]), "r"(b0), "r"(b1));
}
__device__ __forceinline__ float ex2(float x) {
    float r; asm("ex2.approx.ftz.f32 %0, %1;" : "=f"(r) : "f"(x)); return r;
}
__device__ __forceinline__ void split_h16(float x, __half& h, __half& l) {
    h = __float2half_rn(x);
    l = __float2half_rn(x - __half2float(h));
}

// K tile smem geometry: [128 k][64 c] fp16, row pitch 144B (128B data + 16B pad)
#define KPITCH    144
#define TILE_H    18432            // 128 * 144
#define BUF_BYTES 36864            // hi + lo
#define NBUF      4
#define SMEM_TOTAL (NBUF * BUF_BYTES)   // 147456; 1 CTA/SM

__device__ __forceinline__ void load_tile(uint32_t dbuf,
                                          const __half* gKh,
                                          const __half* gKl,
                                          int k0, int t) {
    #pragma unroll
    for (int c = 0; c < 4; ++c) {
        int idx = t + 256 * c;                 // 0..1023
        int row = idx >> 3, ch = idx & 7;
        uint32_t d = dbuf + row * KPITCH + ch * 16;
        const void* sh = gKh + (size_t)(k0 + row) * CCH + ch * 8;
        const void* sl = gKl + (size_t)(k0 + row) * CCH + ch * 8;
        asm volatile("cp.async.cg.shared.global [%0], [%1], 16;" :: "r"(d), "l"(sh));
        asm volatile("cp.async.cg.shared.global [%0], [%1], 16;" :: "r"(d + TILE_H), "l"(sl));
    }
}

// S-GEMM phase A: sacc = (Qh * Kl') * KLINV   (zeroes sacc first)
__device__ __forceinline__ void s_phaseA(uint32_t aLk, float (&sacc)[8][4],
                                         const uint32_t (&qa)[2][4][4]) {
    #pragma unroll
    for (int j = 0; j < 8; ++j)
        #pragma unroll
        for (int r = 0; r < 4; ++r) sacc[j][r] = 0.f;
    #pragma unroll
    for (int s = 0; s < 4; ++s) {
        #pragma unroll
        for (int jg = 0; jg < 2; ++jg) {
            const uint32_t a0 = aLk + (uint32_t)(jg * 32 * KPITCH + 32 * s);
            uint32_t rA[4], rB[4];
            ldsm4(rA, a0);
            ldsm4(rB, a0 + 16 * KPITCH);
            mma16816(sacc[jg * 4 + 0], qa[0][s], rA[0], rA[1]);
            mma16816(sacc[jg * 4 + 1], qa[0][s], rA[2], rA[3]);
            mma16816(sacc[jg * 4 + 2], qa[0][s], rB[0], rB[1]);
            mma16816(sacc[jg * 4 + 3], qa[0][s], rB[2], rB[3]);
        }
    }
    #pragma unroll
    for (int j = 0; j < 8; ++j)
        #pragma unroll
        for (int r = 0; r < 4; ++r) sacc[j][r] *= KLINV;
}

// S-GEMM phase B: sacc += Qh*Kh + Ql*Kh
__device__ __forceinline__ void s_phaseB(uint32_t aHk, float (&sacc)[8][4],
                                         const uint32_t (&qa)[2][4][4]) {
    #pragma unroll
    for (int s = 0; s < 4; ++s) {
        #pragma unroll
        for (int jg = 0; jg < 2; ++jg) {
            const uint32_t a0 = aHk + (uint32_t)(jg * 32 * KPITCH + 32 * s);
            uint32_t rA[4], rB[4];
            ldsm4(rA, a0);
            ldsm4(rB, a0 + 16 * KPITCH);
            mma16816(sacc[jg * 4 + 0], qa[0][s], rA[0], rA[1]);
            mma16816(sacc[jg * 4 + 1], qa[0][s], rA[2], rA[3]);
            mma16816(sacc[jg * 4 + 2], qa[0][s], rB[0], rB[1]);
            mma16816(sacc[jg * 4 + 3], qa[0][s], rB[2], rB[3]);
            mma16816(sacc[jg * 4 + 0], qa[1][s], rA[0], rA[1]);
            mma16816(sacc[jg * 4 + 1], qa[1][s], rA[2], rA[3]);
            mma16816(sacc[jg * 4 + 2], qa[1][s], rB[0], rB[1]);
            mma16816(sacc[jg * 4 + 3], qa[1][s], rB[2], rB[3]);
        }
    }
}

// ---------------------------------------------------------------------------
// prep: one CTA per (h row, batch); emits fp16 hi/lo splits (Kl scaled x256).
// ---------------------------------------------------------------------------
#define VPITCH 67
__global__ void __launch_bounds__(256) prep_kernel(const float* __restrict__ f) {
    const int b = blockIdx.y;
    const int h = blockIdx.x;
    const int t = threadIdx.x;

    __shared__ float vs[CCH * VPITCH];
    __shared__ float fs[CCH * VPITCH];
    __shared__ float rf[4][64];
    __shared__ float sinv[64];

    const float* fb = f + (size_t)b * CCH * PPIX + h * 64;

    #pragma unroll
    for (int i = t; i < CCH * 64; i += 256) {
        int c = i >> 6, w = i & 63;
        const float* base = fb + (size_t)c * PPIX + w;
        float mid = base[0];
        float top = (h > 0)  ? base[-64] : 0.f;
        float bot = (h < 63) ? base[64]  : 0.f;
        vs[c * VPITCH + w + 1] = top + mid + bot;
        fs[c * VPITCH + w + 1] = mid;
    }
    if (t < CCH) { vs[t * VPITCH] = 0.f; vs[t * VPITCH + 65] = 0.f; }
    __syncthreads();

    {
        const int w = t & 63, s = t >> 6;
        float fsq = 0.f;
        #pragma unroll
        for (int cc = 0; cc < 16; ++cc) {
            int c = s * 16 + cc;
            float fv = fs[c * VPITCH + w + 1];
            fsq = fmaf(fv, fv, fsq);
        }
        rf[s][w] = fsq;
    }
    __syncthreads();
    if (t < 64) {
        float F = rf[0][t] + rf[1][t] + rf[2][t] + rf[3][t];
        sinv[t] = 1.f / (sqrtf(F) + 1e-8f);
    }
    __syncthreads();

    const int c = t & 63, s = t >> 6;
    #pragma unroll
    for (int it = 0; it < 16; ++it) {
        const int w = s * 16 + it;
        const float yv = vs[c * VPITCH + w] + vs[c * VPITCH + w + 1] + vs[c * VPITCH + w + 2];
        const float kv = fs[c * VPITCH + w + 1] * sinv[w];
        const size_t rowbase = ((size_t)(b * PPIX + h * 64 + w)) * CCH + c;
        __half hh, ll;
        split_h16(yv, hh, ll);
        g_Qh[rowbase] = hh; g_Ql[rowbase] = ll;
        hh = __float2half_rn(kv);
        g_Kh[rowbase] = hh;
        g_Kl[rowbase] = __float2half_rn((kv - __half2float(hh)) * KLSCALE);
    }
}

// ---------------------------------------------------------------------------
// attn v12: 2-stage cross-tile pipeline. Iteration kt runs softmax(kt)+PV(kt)
// (sacc computed last iteration -> no exposed latency) interleaved with the
// independent S(kt+1) MMAs. 1 CTA/SM (full registers), NBUF=4, loads 3 ahead.
// q-tile 64, 8 warps = 4(qi) x 2(kj).
// ---------------------------------------------------------------------------
__global__ void __launch_bounds__(256) attn_kernel(float* __restrict__ out) {
    extern __shared__ char smem[];
    const uint32_t sb = smem_u32(smem);

    const int b    = blockIdx.y;
    const int q0   = blockIdx.x * 64;
    const int t    = threadIdx.x;
    const int lane = t & 31;
    const int wid  = t >> 5;
    const int qi   = wid >> 1, kj = wid & 1;
    const int qo   = qi * 16,  ko = kj * 64;
    const int g    = lane >> 2, tq = lane & 3;

    // ---- persistent Q A-frags (hi/lo) ----
    uint32_t qa[2][4][4];
    #pragma unroll
    for (int hl = 0; hl < 2; ++hl) {
        const __half* Qsrc = hl ? g_Ql : g_Qh;
        const __half* r0 = Qsrc + (size_t)(b * PPIX + q0 + qo + g) * CCH;
        const __half* r8 = r0 + 8 * CCH;
        #pragma unroll
        for (int s = 0; s < 4; ++s) {
            int c0 = 16 * s + 2 * tq;
            qa[hl][s][0] = *(const uint32_t*)(r0 + c0);
            qa[hl][s][1] = *(const uint32_t*)(r8 + c0);
            qa[hl][s][2] = *(const uint32_t*)(r0 + c0 + 8);
            qa[hl][s][3] = *(const uint32_t*)(r8 + c0 + 8);
        }
    }

    float oacc[8][4];
    #pragma unroll
    for (int n = 0; n < 8; ++n)
        #pragma unroll
        for (int r = 0; r < 4; ++r) oacc[n][r] = 0.f;
    float lsum[2] = {0.f, 0.f};
    float M[2] = {-1e30f, -1e30f};

    const __half* gKh = g_Kh + (size_t)b * PPIX * CCH;
    const __half* gKl = g_Kl + (size_t)b * PPIX * CCH;

    // prologue: prefetch tiles 0,1,2 (3 commit groups)
    load_tile(sb,                 gKh, gKl,   0, t);
    asm volatile("cp.async.commit_group;" ::: "memory");
    load_tile(sb + BUF_BYTES,     gKh, gKl, 128, t);
    asm volatile("cp.async.commit_group;" ::: "memory");
    load_tile(sb + 2 * BUF_BYTES, gKh, gKl, 256, t);
    asm volatile("cp.async.commit_group;" ::: "memory");

    const uint32_t soff  = (uint32_t)((((lane >> 4) * 8) + (lane & 7)) * KPITCH
                                      + ((lane >> 3) & 1) * 16);
    const uint32_t sko = soff + (uint32_t)(ko * KPITCH);
    const uint32_t laneoff = (uint32_t)(((lane & 7) + 8 * ((lane >> 3) & 1)) * KPITCH
                                        + (lane >> 4) * 16);

    float saccA[8][4], saccB[8][4];

    // S(0) into saccA
    asm volatile("cp.async.wait_group 2;" ::: "memory");
    __syncthreads();
    s_phaseA(sb + TILE_H + sko, saccA, qa);
    s_phaseB(sb + sko,          saccA, qa);

// One pipeline step: softmax+PV of tile KT (from CUR), S of tile KT+1 (into NXT).
#define BODY(KT, CUR, NXT)                                                     \
    {                                                                          \
        asm volatile("cp.async.wait_group 1;" ::: "memory");                   \
        __syncthreads();                                                       \
        if ((KT) + 3 < 32)                                                     \
            load_tile(sb + (uint32_t)(((KT) + 3) & 3) * BUF_BYTES,             \
                      gKh, gKl, ((KT) + 3) * 128, t);                          \
        asm volatile("cp.async.commit_group;" ::: "memory");                   \
        const uint32_t aPV = sb + (uint32_t)((KT) & 3) * BUF_BYTES;            \
        const uint32_t aS  = sb + (uint32_t)(((KT) + 1) & 3) * BUF_BYTES;      \
        if ((KT) + 1 < 32) s_phaseA(aS + TILE_H + sko, NXT, qa);               \
        float t0 = -1e30f, t1 = -1e30f;                                        \
        _Pragma("unroll")                                                      \
        for (int j = 0; j < 8; ++j) {                                          \
            t0 = fmaxf(t0, fmaxf(CUR[j][0], CUR[j][1]));                       \
            t1 = fmaxf(t1, fmaxf(CUR[j][2], CUR[j][3]));                       \
        }                                                                      \
        t0 = fmaxf(t0, __shfl_xor_sync(0xffffffffu, t0, 1));                   \
        t0 = fmaxf(t0, __shfl_xor_sync(0xffffffffu, t0, 2));                   \
        t1 = fmaxf(t1, __shfl_xor_sync(0xffffffffu, t1, 1));                   \
        t1 = fmaxf(t1, __shfl_xor_sync(0xffffffffu, t1, 2));                   \
        const float Mn0 = fmaxf(M[0], t0 * LOG2E);                             \
        const float Mn1 = fmaxf(M[1], t1 * LOG2E);                             \
        if (!__all_sync(0xffffffffu, (Mn0 == M[0]) && (Mn1 == M[1]))) {        \
            const float c0 = ex2(M[0] - Mn0);                                  \
            const float c1 = ex2(M[1] - Mn1);                                  \
            M[0] = Mn0; M[1] = Mn1;                                            \
            lsum[0] *= c0; lsum[1] *= c1;                                      \
            _Pragma("unroll")                                                  \
            for (int n = 0; n < 8; ++n) {                                      \
                oacc[n][0] *= c0; oacc[n][1] *= c0;                            \
                oacc[n][2] *= c1; oacc[n][3] *= c1;                            \
            }                                                                  \
        }                                                                      \
        if ((KT) + 1 < 32) s_phaseB(aS + sko, NXT, qa);                        \
        const float sh0 = PSH - Mn0, sh1 = PSH - Mn1;                          \
        _Pragma("unroll")                                                      \
        for (int s2 = 0; s2 < 4; ++s2) {                                       \
            uint32_t pah[4];                                                   \
            _Pragma("unroll")                                                  \
            for (int jj = 0; jj < 2; ++jj) {                                   \
                const int j = 2 * s2 + jj;                                     \
                float p0 = ex2(fmaf(CUR[j][0], LOG2E, sh0));                   \
                float p1 = ex2(fmaf(CUR[j][1], LOG2E, sh0));                   \
                float p2 = ex2(fmaf(CUR[j][2], LOG2E, sh1));                   \
                float p3 = ex2(fmaf(CUR[j][3], LOG2E, sh1));                   \
                lsum[0] += p0 + p1;                                            \
                lsum[1] += p2 + p3;                                            \
                __half2 h01 = __floats2half2_rn(p0, p1);                       \
                __half2 h23 = __floats2half2_rn(p2, p3);                       \
                pah[jj * 2]     = *(uint32_t*)&h01;                            \
                pah[jj * 2 + 1] = *(uint32_t*)&h23;                            \
            }                                                                  \
            const uint32_t base = (uint32_t)((ko + 16 * s2) * KPITCH) + laneoff; \
            _Pragma("unroll")                                                  \
            for (int jpg = 0; jpg < 2; ++jpg) {                                \
                uint32_t bh0[4], bh1[4];                                       \
                ldsm4t(bh0, aPV + base + (jpg * 2 + 0) * 32);                  \
                ldsm4t(bh1, aPV + base + (jpg * 2 + 1) * 32);                  \
                const int jpA = jpg * 2, jpB = jpg * 2 + 1;                    \
                mma16816(oacc[2 * jpA],     pah, bh0[0], bh0[1]);              \
                mma16816(oacc[2 * jpA + 1], pah, bh0[2], bh0[3]);              \
                mma16816(oacc[2 * jpB],     pah, bh1[0], bh1[1]);              \
                mma16816(oacc[2 * jpB + 1], pah, bh1[2], bh1[3]);              \
            }                                                                  \
        }                                                                      \
    }

    #pragma unroll 1
    for (int kt2 = 0; kt2 < 16; ++kt2) {
        const int kt = kt2 * 2;
        BODY(kt,     saccA, saccB);
        BODY(kt + 1, saccB, saccA);
    }
#undef BODY

    // ---- epilogue: quad-reduce lsum; merge k-warps with max reconciliation ----
    #pragma unroll
    for (int h = 0; h < 2; ++h) {
        lsum[h] += __shfl_xor_sync(0xffffffffu, lsum[h], 1);
        lsum[h] += __shfl_xor_sync(0xffffffffu, lsum[h], 2);
    }

    float* redO = (float*)smem;                    // [4 qi][32 lanes][33]
    float* redL = (float*)(smem + 17408);          // [64] row lsums
    float* redM = (float*)(smem + 17664);          // [64] row maxes
    float* stg  = (float*)(smem + 36864);          // [64 c][68 q]

    __syncthreads();   // all PV reads done before reusing smem

    if (kj == 1) {
        float* dst = redO + (qi * 32 + lane) * 33;
        #pragma unroll
        for (int n = 0; n < 8; ++n)
            #pragma unroll
            for (int r = 0; r < 4; ++r)
                dst[n * 4 + r] = oacc[n][r];
        if (tq == 0) {
            redL[qi * 16 + g]     = lsum[0];
            redL[qi * 16 + 8 + g] = lsum[1];
            redM[qi * 16 + g]     = M[0];
            redM[qi * 16 + 8 + g] = M[1];
        }
    }
    __syncthreads();

    if (kj == 0) {
        const float* src = redO + (qi * 32 + lane) * 33;
        float fme[2], fot[2], inv[2];
        #pragma unroll
        for (int h = 0; h < 2; ++h) {
            const float Mo = redM[qi * 16 + 8 * h + g];
            const float lo = redL[qi * 16 + 8 * h + g];
            const float Mt = fmaxf(M[h], Mo);
            fme[h] = ex2(M[h] - Mt);
            fot[h] = ex2(Mo - Mt);
            inv[h] = 1.f / (lsum[h] * fme[h] + lo * fot[h]);
        }
        #pragma unroll
        for (int n = 0; n < 8; ++n)
            #pragma unroll
            for (int r = 0; r < 4; ++r) {
                const int h = r >> 1;
                float v = (oacc[n][r] * fme[h] + src[n * 4 + r] * fot[h]) * inv[h];
                int q = qo + g + ((r & 2) ? 8 : 0);
                int c = 8 * n + 2 * tq + (r & 1);
                stg[c * 68 + q] = v;
            }
    }
    __syncthreads();

    float* ob = out + (size_t)b * CCH * PPIX;
    #pragma unroll
    for (int it = 0; it < 4; ++it) {
        int i = t + 256 * it;
        int row = i >> 4, f4 = i & 15;
        float4 v = *(const float4*)(stg + row * 68 + f4 * 4);
        *(float4*)(ob + row * PPIX + q0 + 4 * f4) = v;
    }
}

// ---------------------------------------------------------------------------
extern "C" void kernel_launch(void* const* d_in, const int* in_sizes, int n_in,
                              void* d_out, int out_size) {
    const float* f = (const float*)d_in[0];   // foreground [4,64,64,64] fp32
    float* out = (float*)d_out;               // [4,64,64,64] fp32

    prep_kernel<<<dim3(64, 4), 256>>>(f);

    cudaFuncSetAttribute(attn_kernel, cudaFuncAttributeMaxDynamicSharedMemorySize, SMEM_TOTAL);
    attn_kernel<<<dim3(64, 4), 256, SMEM_TOTAL>>>(out);
}

// round 16
// speedup vs baseline: 1.1060x; 1.1060x over previous
#include <cuda_runtime.h>
#include <cuda_fp16.h>
#include <stdint.h>
#include <math.h>

// Problem constants: B=4, C=64, H=W=64, P=4096.
#define BATCH 4
#define CCH   64
#define PPIX  4096
#define LOG2E 1.4426950408889634f
#define PSH   14.0f                 // pack scale: p' = 2^(s*log2e - M + 14) <= 2^14
#define KLSCALE 256.0f
#define KLINV  0.00390625f

// ---------------------------------------------------------------------------
// Device scratch. fp16 split x = hi + lo (~22 bits). Kl stored *256 so its
// elements sit in fp16 normal range.
// ---------------------------------------------------------------------------
__device__ __half g_Qh[BATCH * PPIX * CCH];  // Y boxsum  [b][p][c]
__device__ __half g_Ql[BATCH * PPIX * CCH];
__device__ __half g_Kh[BATCH * PPIX * CCH];  // K-hat     [b][p][c]  (also V)
__device__ __half g_Kl[BATCH * PPIX * CCH];  // (K - Kh) * 256

// ---------------------------------------------------------------------------
// helpers (baseline PTX only: mma.sync / ldmatrix / cp.async)
// ---------------------------------------------------------------------------
__device__ __forceinline__ uint32_t smem_u32(const void* p) {
    uint32_t a;
    asm("{ .reg .u64 t; cvta.to.shared.u64 t, %1; cvt.u32.u64 %0, t; }" : "=r"(a) : "l"(p));
    return a;
}
__device__ __forceinline__ void ldsm4(uint32_t* r, uint32_t addr) {   // non-trans
    asm volatile("ldmatrix.sync.aligned.m8n8.x4.shared.b16 {%0,%1,%2,%3}, [%4];"
        : "=r"(r[0]), "=r"(r[1]), "=r"(r[2]), "=r"(r[3]) : "r"(addr));
}
__device__ __forceinline__ void ldsm4t(uint32_t* r, uint32_t addr) {  // trans
    asm volatile("ldmatrix.sync.aligned.m8n8.x4.trans.shared.b16 {%0,%1,%2,%3}, [%4];"
        : "=r"(r[0]), "=r"(r[1]), "=r"(r[2]), "=r"(r[3]) : "r"(addr));
}
__device__ __forceinline__ void mma16816(float* d, const uint32_t* a, uint32_t b0, uint32_t b1) {
    asm volatile(
        "mma.sync.aligned.m16n8k16.row.col.f32.f16.f16.f32 "
        "{%0,%1,%2,%3}, {%4,%5,%6,%7}, {%8,%9}, {%0,%1,%2,%3};"
        : "+f"(d[0]), "+f"(d[1]), "+f"(d[2]), "+f"(d[3])
        : "r"(a[0]), "r"(a[1]), "r"(a[2]), "r"(a[3]), "r"(b0), "r"(b1));
}
__device__ __forceinline__ float ex2(float x) {
    float r; asm("ex2.approx.ftz.f32 %0, %1;" : "=f"(r) : "f"(x)); return r;
}
__device__ __forceinline__ void split_h16(float x, __half& h, __half& l) {
    h = __float2half_rn(x);
    l = __float2half_rn(x - __half2float(h));
}

// K tile smem geometry: [128 k][64 c] fp16, row pitch 144B (128B data + 16B pad)
#define KPITCH    144
#define TILE_H    18432            // 128 * 144
#define BUF_BYTES 36864            // hi + lo
#define NBUF      3
#define SMEM_TOTAL (NBUF * BUF_BYTES)   // 110592; 2 CTAs/SM -> 221KB, fits

__device__ __forceinline__ void load_tile(uint32_t dbuf,
                                          const __half* gKh,
                                          const __half* gKl,
                                          int k0, int t) {
    #pragma unroll
    for (int c = 0; c < 4; ++c) {
        int idx = t + 256 * c;                 // 0..1023
        int row = idx >> 3, ch = idx & 7;
        uint32_t d = dbuf + row * KPITCH + ch * 16;
        const void* sh = gKh + (size_t)(k0 + row) * CCH + ch * 8;
        const void* sl = gKl + (size_t)(k0 + row) * CCH + ch * 8;
        asm volatile("cp.async.cg.shared.global [%0], [%1], 16;" :: "r"(d), "l"(sh));
        asm volatile("cp.async.cg.shared.global [%0], [%1], 16;" :: "r"(d + TILE_H), "l"(sl));
    }
}

// ---------------------------------------------------------------------------
// prep v3: one CTA per (h row, batch). Phase-3 emits half2 stores (full 128B
// line per warp per array) instead of scalar 2B stores.
// ---------------------------------------------------------------------------
#define VPITCH 67
__global__ void __launch_bounds__(256) prep_kernel(const float* __restrict__ f) {
    const int b = blockIdx.y;
    const int h = blockIdx.x;
    const int t = threadIdx.x;

    __shared__ float vs[CCH * VPITCH];
    __shared__ float fs[CCH * VPITCH];
    __shared__ float rf[4][64];
    __shared__ float sinv[64];

    const float* fb = f + (size_t)b * CCH * PPIX + h * 64;

    #pragma unroll
    for (int i = t; i < CCH * 64; i += 256) {
        int c = i >> 6, w = i & 63;
        const float* base = fb + (size_t)c * PPIX + w;
        float mid = base[0];
        float top = (h > 0)  ? base[-64] : 0.f;
        float bot = (h < 63) ? base[64]  : 0.f;
        vs[c * VPITCH + w + 1] = top + mid + bot;
        fs[c * VPITCH + w + 1] = mid;
    }
    if (t < CCH) { vs[t * VPITCH] = 0.f; vs[t * VPITCH + 65] = 0.f; }
    __syncthreads();

    {
        const int w = t & 63, s = t >> 6;
        float fsq = 0.f;
        #pragma unroll
        for (int cc = 0; cc < 16; ++cc) {
            int c = s * 16 + cc;
            float fv = fs[c * VPITCH + w + 1];
            fsq = fmaf(fv, fv, fsq);
        }
        rf[s][w] = fsq;
    }
    __syncthreads();
    if (t < 64) {
        float F = rf[0][t] + rf[1][t] + rf[2][t] + rf[3][t];
        sinv[t] = 1.f / (sqrtf(F) + 1e-8f);
    }
    __syncthreads();

    // Phase 3: thread owns channel pair c2,c2+1; half2 stores (coalesced 128B).
    const int c2 = (t & 31) * 2;
    const int s  = t >> 5;              // 0..7
    #pragma unroll
    for (int it = 0; it < 8; ++it) {
        const int w = s * 8 + it;
        const float si = sinv[w];
        float yv0 = vs[c2 * VPITCH + w] + vs[c2 * VPITCH + w + 1] + vs[c2 * VPITCH + w + 2];
        float yv1 = vs[(c2 + 1) * VPITCH + w] + vs[(c2 + 1) * VPITCH + w + 1] + vs[(c2 + 1) * VPITCH + w + 2];
        float kv0 = fs[c2 * VPITCH + w + 1] * si;
        float kv1 = fs[(c2 + 1) * VPITCH + w + 1] * si;

        __half yh0, yl0, yh1, yl1;
        split_h16(yv0, yh0, yl0);
        split_h16(yv1, yh1, yl1);
        __half kh0 = __float2half_rn(kv0);
        __half kh1 = __float2half_rn(kv1);
        __half kl0 = __float2half_rn((kv0 - __half2float(kh0)) * KLSCALE);
        __half kl1 = __float2half_rn((kv1 - __half2float(kh1)) * KLSCALE);

        const size_t rowbase = ((size_t)(b * PPIX + h * 64 + w)) * CCH + c2;
        *(__half2*)(g_Qh + rowbase) = __halves2half2(yh0, yh1);
        *(__half2*)(g_Ql + rowbase) = __halves2half2(yl0, yl1);
        *(__half2*)(g_Kh + rowbase) = __halves2half2(kh0, kh1);
        *(__half2*)(g_Kl + rowbase) = __halves2half2(kl0, kl1);
    }
}

// ---------------------------------------------------------------------------
// attn (R13 verbatim — best measured config): fp16 + online max + ldmatrix,
// triple-buffered (1 barrier per kt), MUFU ex2, vote-skipped O-rescale.
// q-tile 64, 8 warps = 4(qi) x 2(kj), 2 CTAs/SM.
// ---------------------------------------------------------------------------
__global__ void __launch_bounds__(256, 2) attn_kernel(float* __restrict__ out) {
    extern __shared__ char smem[];
    const uint32_t sb = smem_u32(smem);

    const int b    = blockIdx.y;
    const int q0   = blockIdx.x * 64;
    const int t    = threadIdx.x;
    const int lane = t & 31;
    const int wid  = t >> 5;
    const int qi   = wid >> 1, kj = wid & 1;
    const int qo   = qi * 16,  ko = kj * 64;
    const int g    = lane >> 2, tq = lane & 3;

    // ---- persistent Q A-frags (hi/lo) ----
    uint32_t qa[2][4][4];
    #pragma unroll
    for (int hl = 0; hl < 2; ++hl) {
        const __half* Qsrc = hl ? g_Ql : g_Qh;
        const __half* r0 = Qsrc + (size_t)(b * PPIX + q0 + qo + g) * CCH;
        const __half* r8 = r0 + 8 * CCH;
        #pragma unroll
        for (int s = 0; s < 4; ++s) {
            int c0 = 16 * s + 2 * tq;
            qa[hl][s][0] = *(const uint32_t*)(r0 + c0);
            qa[hl][s][1] = *(const uint32_t*)(r8 + c0);
            qa[hl][s][2] = *(const uint32_t*)(r0 + c0 + 8);
            qa[hl][s][3] = *(const uint32_t*)(r8 + c0 + 8);
        }
    }

    float oacc[8][4];
    #pragma unroll
    for (int n = 0; n < 8; ++n)
        #pragma unroll
        for (int r = 0; r < 4; ++r) oacc[n][r] = 0.f;
    float lsum[2] = {0.f, 0.f};
    float M[2] = {-1e30f, -1e30f};     // running row max, log2 units

    const __half* gKh = g_Kh + (size_t)b * PPIX * CCH;
    const __half* gKl = g_Kl + (size_t)b * PPIX * CCH;

    // prologue: prefetch tiles 0 and 1 as separate commit groups
    load_tile(sb, gKh, gKl, 0, t);
    asm volatile("cp.async.commit_group;" ::: "memory");
    load_tile(sb + BUF_BYTES, gKh, gKl, 128, t);
    asm volatile("cp.async.commit_group;" ::: "memory");

    // ldmatrix per-thread offsets
    const uint32_t soff  = (uint32_t)((((lane >> 4) * 8) + (lane & 7)) * KPITCH
                                      + ((lane >> 3) & 1) * 16);
    const uint32_t laneoff = (uint32_t)(((lane & 7) + 8 * ((lane >> 3) & 1)) * KPITCH
                                        + (lane >> 4) * 16);

    int buf = 0;
    for (int kt = 0; kt < 32; ++kt) {
        // tile kt complete (all groups but the newest have drained)
        asm volatile("cp.async.wait_group 1;" ::: "memory");
        __syncthreads();   // visibility of tile kt; prior reads of the buffer
                           // tile kt+2 will overwrite are done
        if (kt + 2 < 32) {
            int nb = buf + 2; if (nb >= NBUF) nb -= NBUF;
            load_tile(sb + (uint32_t)nb * BUF_BYTES, gKh, gKl, (kt + 2) * 128, t);
        }
        asm volatile("cp.async.commit_group;" ::: "memory");

        const uint32_t aH = sb + (uint32_t)buf * BUF_BYTES;
        const uint32_t aL = aH + TILE_H;
        const uint32_t sbaseH = aH + soff + (uint32_t)(ko * KPITCH);
        const uint32_t sbaseL = aL + soff + (uint32_t)(ko * KPITCH);
        if (++buf >= NBUF) buf -= NBUF;

        float sacc[8][4];
        #pragma unroll
        for (int j = 0; j < 8; ++j)
            #pragma unroll
            for (int r = 0; r < 4; ++r) sacc[j][r] = 0.f;

        // ---- Phase A: Qh * Kl' (scaled cross term) ----
        #pragma unroll
        for (int s = 0; s < 4; ++s) {
            #pragma unroll
            for (int jg = 0; jg < 2; ++jg) {
                const uint32_t a0 = sbaseL + (uint32_t)(jg * 32 * KPITCH + 32 * s);
                uint32_t rA[4], rB[4];
                ldsm4(rA, a0);
                ldsm4(rB, a0 + 16 * KPITCH);
                mma16816(sacc[jg * 4 + 0], qa[0][s], rA[0], rA[1]);
                mma16816(sacc[jg * 4 + 1], qa[0][s], rA[2], rA[3]);
                mma16816(sacc[jg * 4 + 2], qa[0][s], rB[0], rB[1]);
                mma16816(sacc[jg * 4 + 3], qa[0][s], rB[2], rB[3]);
            }
        }
        #pragma unroll
        for (int j = 0; j < 8; ++j)
            #pragma unroll
            for (int r = 0; r < 4; ++r) sacc[j][r] *= KLINV;

        // ---- Phase B: Qh*Kh + Ql*Kh ----
        #pragma unroll
        for (int s = 0; s < 4; ++s) {
            #pragma unroll
            for (int jg = 0; jg < 2; ++jg) {
                const uint32_t a0 = sbaseH + (uint32_t)(jg * 32 * KPITCH + 32 * s);
                uint32_t rA[4], rB[4];
                ldsm4(rA, a0);
                ldsm4(rB, a0 + 16 * KPITCH);
                mma16816(sacc[jg * 4 + 0], qa[0][s], rA[0], rA[1]);
                mma16816(sacc[jg * 4 + 1], qa[0][s], rA[2], rA[3]);
                mma16816(sacc[jg * 4 + 2], qa[0][s], rB[0], rB[1]);
                mma16816(sacc[jg * 4 + 3], qa[0][s], rB[2], rB[3]);
                mma16816(sacc[jg * 4 + 0], qa[1][s], rA[0], rA[1]);
                mma16816(sacc[jg * 4 + 1], qa[1][s], rA[2], rA[3]);
                mma16816(sacc[jg * 4 + 2], qa[1][s], rB[0], rB[1]);
                mma16816(sacc[jg * 4 + 3], qa[1][s], rB[2], rB[3]);
            }
        }

        // ---- online max update (vote-skipped rescale) ----
        float t0 = -1e30f, t1 = -1e30f;
        #pragma unroll
        for (int j = 0; j < 8; ++j) {
            t0 = fmaxf(t0, fmaxf(sacc[j][0], sacc[j][1]));
            t1 = fmaxf(t1, fmaxf(sacc[j][2], sacc[j][3]));
        }
        t0 = fmaxf(t0, __shfl_xor_sync(0xffffffffu, t0, 1));
        t0 = fmaxf(t0, __shfl_xor_sync(0xffffffffu, t0, 2));
        t1 = fmaxf(t1, __shfl_xor_sync(0xffffffffu, t1, 1));
        t1 = fmaxf(t1, __shfl_xor_sync(0xffffffffu, t1, 2));
        const float Mn0 = fmaxf(M[0], t0 * LOG2E);
        const float Mn1 = fmaxf(M[1], t1 * LOG2E);
        if (!__all_sync(0xffffffffu, (Mn0 == M[0]) && (Mn1 == M[1]))) {
            const float c0 = ex2(M[0] - Mn0);
            const float c1 = ex2(M[1] - Mn1);
            M[0] = Mn0; M[1] = Mn1;
            lsum[0] *= c0; lsum[1] *= c1;
            #pragma unroll
            for (int n = 0; n < 8; ++n) {
                oacc[n][0] *= c0; oacc[n][1] *= c0;
                oacc[n][2] *= c1; oacc[n][3] *= c1;
            }
        }

        // ---- pack P (fp16, scale 2^PSH) ----
        uint32_t pah[4][4];
        const float sh0 = PSH - Mn0, sh1 = PSH - Mn1;
        #pragma unroll
        for (int j = 0; j < 8; ++j) {
            float p0 = ex2(fmaf(sacc[j][0], LOG2E, sh0));
            float p1 = ex2(fmaf(sacc[j][1], LOG2E, sh0));
            float p2 = ex2(fmaf(sacc[j][2], LOG2E, sh1));
            float p3 = ex2(fmaf(sacc[j][3], LOG2E, sh1));
            lsum[0] += p0 + p1;
            lsum[1] += p2 + p3;
            const int s2 = j >> 1, r = (j & 1) * 2;
            __half2 h01 = __floats2half2_rn(p0, p1);
            __half2 h23 = __floats2half2_rn(p2, p3);
            pah[s2][r]     = *(uint32_t*)&h01;
            pah[s2][r + 1] = *(uint32_t*)&h23;
        }

        // ---- O += P.Vh, single fp16 pass ----
        #pragma unroll
        for (int s2 = 0; s2 < 4; ++s2) {
            const uint32_t base = (uint32_t)((ko + 16 * s2) * KPITCH) + laneoff;
            #pragma unroll
            for (int jpg = 0; jpg < 2; ++jpg) {
                uint32_t bh0[4], bh1[4];
                ldsm4t(bh0, aH + base + (jpg * 2 + 0) * 32);
                ldsm4t(bh1, aH + base + (jpg * 2 + 1) * 32);
                const int jpA = jpg * 2, jpB = jpg * 2 + 1;
                mma16816(oacc[2 * jpA],     pah[s2], bh0[0], bh0[1]);
                mma16816(oacc[2 * jpA + 1], pah[s2], bh0[2], bh0[3]);
                mma16816(oacc[2 * jpB],     pah[s2], bh1[0], bh1[1]);
                mma16816(oacc[2 * jpB + 1], pah[s2], bh1[2], bh1[3]);
            }
        }
    }

    // ---- epilogue: quad-reduce lsum; merge k-warps with max reconciliation ----
    #pragma unroll
    for (int h = 0; h < 2; ++h) {
        lsum[h] += __shfl_xor_sync(0xffffffffu, lsum[h], 1);
        lsum[h] += __shfl_xor_sync(0xffffffffu, lsum[h], 2);
    }

    float* redO = (float*)smem;                    // [4 qi][32 lanes][33]  (buf0)
    float* redL = (float*)(smem + 17408);          // [64] row lsums
    float* redM = (float*)(smem + 17664);          // [64] row maxes
    float* stg  = (float*)(smem + 36864);          // [64 c][68 q]          (buf1)

    if (kj == 1) {
        float* dst = redO + (qi * 32 + lane) * 33;
        #pragma unroll
        for (int n = 0; n < 8; ++n)
            #pragma unroll
            for (int r = 0; r < 4; ++r)
                dst[n * 4 + r] = oacc[n][r];
        if (tq == 0) {
            redL[qi * 16 + g]     = lsum[0];
            redL[qi * 16 + 8 + g] = lsum[1];
            redM[qi * 16 + g]     = M[0];
            redM[qi * 16 + 8 + g] = M[1];
        }
    }
    __syncthreads();

    if (kj == 0) {
        const float* src = redO + (qi * 32 + lane) * 33;
        float fme[2], fot[2], inv[2];
        #pragma unroll
        for (int h = 0; h < 2; ++h) {
            const float Mo = redM[qi * 16 + 8 * h + g];
            const float lo = redL[qi * 16 + 8 * h + g];
            const float Mt = fmaxf(M[h], Mo);
            fme[h] = ex2(M[h] - Mt);
            fot[h] = ex2(Mo - Mt);
            inv[h] = 1.f / (lsum[h] * fme[h] + lo * fot[h]);
        }
        #pragma unroll
        for (int n = 0; n < 8; ++n)
            #pragma unroll
            for (int r = 0; r < 4; ++r) {
                const int h = r >> 1;
                float v = (oacc[n][r] * fme[h] + src[n * 4 + r] * fot[h]) * inv[h];
                int q = qo + g + ((r & 2) ? 8 : 0);
                int c = 8 * n + 2 * tq + (r & 1);
                stg[c * 68 + q] = v;
            }
    }
    __syncthreads();

    float* ob = out + (size_t)b * CCH * PPIX;
    #pragma unroll
    for (int it = 0; it < 4; ++it) {
        int i = t + 256 * it;
        int row = i >> 4, f4 = i & 15;
        float4 v = *(const float4*)(stg + row * 68 + f4 * 4);
        *(float4*)(ob + row * PPIX + q0 + 4 * f4) = v;
    }
}

// ---------------------------------------------------------------------------
extern "C" void kernel_launch(void* const* d_in, const int* in_sizes, int n_in,
                              void* d_out, int out_size) {
    const float* f = (const float*)d_in[0];   // foreground [4,64,64,64] fp32
    float* out = (float*)d_out;               // [4,64,64,64] fp32

    prep_kernel<<<dim3(64, 4), 256>>>(f);

    cudaFuncSetAttribute(attn_kernel, cudaFuncAttributeMaxDynamicSharedMemorySize, SMEM_TOTAL);
    attn_kernel<<<dim3(64, 4), 256, SMEM_TOTAL>>>(out);
}